// round 14
// baseline (speedup 1.0000x reference)
#include <cuda_runtime.h>
#include <cuda_fp16.h>
#include <cstdint>

#define EMBED   1024
#define NHEAD   16
#define HD      64
#define SEQ     2048
#define BATCH   4
#define MROWS   (BATCH * SEQ)      /* 8192 */
#define QKVN    (3 * EMBED)        /* 3072 */
#define KDIM    1024

// ---------------------------------------------------------------------------
// Scratch (device globals -- runtime allocation is forbidden)
// ---------------------------------------------------------------------------
static __device__ __half g_qkv1[(size_t)MROWS * QKVN];       // qkv fp16
static __device__ __half g_att1[(size_t)MROWS * KDIM];       // attn out fp16
static __device__ __half g_wq2 [(size_t)QKVN  * KDIM];       // w_qkv^T fp16
static __device__ __half g_wo2 [(size_t)EMBED * KDIM];       // w_out^T fp16

// ---------------------------------------------------------------------------
// PTX helpers (baseline ISA, sm_80-compatible encodings only)
// ---------------------------------------------------------------------------
__device__ __forceinline__ uint32_t smem_u32(const void* p) {
    uint32_t a;
    asm("{ .reg .u64 t; cvta.to.shared.u64 t, %1; cvt.u32.u64 %0, t; }"
        : "=r"(a) : "l"(p));
    return a;
}
__device__ __forceinline__ void cpasync16(uint32_t dst, const void* src) {
    asm volatile("cp.async.cg.shared.global [%0], [%1], 16;"
        :: "r"(dst), "l"(src) : "memory");
}
#define CP_COMMIT() asm volatile("cp.async.commit_group;" ::: "memory")

__device__ __forceinline__ void ldsm4(uint32_t* r, uint32_t addr) {
    asm volatile("ldmatrix.sync.aligned.m8n8.x4.shared.b16 {%0,%1,%2,%3}, [%4];"
        : "=r"(r[0]), "=r"(r[1]), "=r"(r[2]), "=r"(r[3]) : "r"(addr));
}
__device__ __forceinline__ void ldsm4t(uint32_t* r, uint32_t addr) {
    asm volatile("ldmatrix.sync.aligned.m8n8.x4.trans.shared.b16 {%0,%1,%2,%3}, [%4];"
        : "=r"(r[0]), "=r"(r[1]), "=r"(r[2]), "=r"(r[3]) : "r"(addr));
}
// fp16 MMA, fp32 accumulate
__device__ __forceinline__ void mma16816(float* c, const uint32_t* a,
                                         uint32_t b0, uint32_t b1) {
    asm volatile(
        "mma.sync.aligned.m16n8k16.row.col.f32.f16.f16.f32 "
        "{%0,%1,%2,%3}, {%4,%5,%6,%7}, {%8,%9}, {%0,%1,%2,%3};"
        : "+f"(c[0]), "+f"(c[1]), "+f"(c[2]), "+f"(c[3])
        : "r"(a[0]), "r"(a[1]), "r"(a[2]), "r"(a[3]), "r"(b0), "r"(b1));
}
__device__ __forceinline__ float ex2(float x) {
    float y; asm("ex2.approx.f32 %0, %1;" : "=f"(y) : "f"(x)); return y;
}
__device__ __forceinline__ uint32_t pack_h2(float x, float y) {
    __half2 h = __floats2half2_rn(x, y);
    return *(uint32_t*)&h;
}

// ---------------------------------------------------------------------------
// operand prep: weights only (x cast is fused into GEMM1's A-path).
// blocks [0, 3072)      : w_qkv transpose+cast (96 x 32 tiles)
// blocks [3072, 4096)   : w_out transpose+cast (32 x 32 tiles)
// ---------------------------------------------------------------------------
#define NB_WQ   3072
#define PREP_BLOCKS (NB_WQ + 1024)

__device__ __forceinline__ void transpose_tile(
    const float* __restrict__ w, __half* __restrict__ out, int N,
    int n0, int k0, float (*t)[33], int tid)
{
    const int tx = tid & 31, ty = tid >> 5;
#pragma unroll
    for (int i = 0; i < 4; i++)
        t[ty + 8 * i][tx] = w[(size_t)(k0 + ty + 8 * i) * N + n0 + tx];
    __syncthreads();
#pragma unroll
    for (int i = 0; i < 4; i++) {
        int nl = ty + 8 * i;
        out[(size_t)(n0 + nl) * KDIM + k0 + tx] = __float2half_rn(t[tx][nl]);
    }
}

__global__ __launch_bounds__(256) void prep_w(
    const float* __restrict__ wq, __half* __restrict__ wq2,
    const float* __restrict__ wo, __half* __restrict__ wo2)
{
    __shared__ float t[32][33];
    const int b = blockIdx.x, tid = threadIdx.x;
    if (b < NB_WQ) {
        transpose_tile(wq, wq2, QKVN, (b % 96) * 32, (b / 96) * 32, t, tid);
    } else {
        int bb = b - NB_WQ;
        transpose_tile(wo, wo2, EMBED, (bb % 32) * 32, (bb / 32) * 32, t, tid);
    }
}

// ---------------------------------------------------------------------------
// mma.sync fp16 GEMM (2 CTAs/SM). CTA 128x128, warp tile 64x32 (2Mx4N),
// BK=64, 3-stage pipeline (32KB/stage), chunk swizzle c^(r&7).
// AF32=true : A is fp32 in gmem; A-chunks go LDG.128 x2 -> cvt -> STS.128
//             (inline cast; B stays on cp.async).
// AF32=false: A is fp16; both tiles via cp.async.
// SPLIT=true : C fp16 [M,ldc] + bias.   SPLIT=false: C fp32 [M,ldc] + bias.
// ---------------------------------------------------------------------------
#define BM 128
#define BN 128
#define BK 64
#define NK (KDIM / BK)            /* 16 */
#define NSTAGE 3
#define STG_BYTES 32768
#define GEMM_SMEM (NSTAGE * STG_BYTES)   /* 98304 */

__device__ __forceinline__ void gemm_load_stage_h(
    uint32_t sbase, const __half* __restrict__ A, const __half* __restrict__ B1,
    int m0, int n0, int kt, int tid)
{
    const int k0 = kt * BK;
#pragma unroll
    for (int i = 0; i < 4; i++) {
        int id = tid + 256 * i;            // 0..1023: 128 rows x 8 chunks
        int r = id >> 3;
        int c = id & 7;
        uint32_t soff = r * 128 + ((c ^ (r & 7)) << 4);
        cpasync16(sbase + soff,         A  + (size_t)(m0 + r) * KDIM + k0 + c * 8);
        cpasync16(sbase + 16384 + soff, B1 + (size_t)(n0 + r) * KDIM + k0 + c * 8);
    }
}

__device__ __forceinline__ void gemm_load_stage_f32(
    uint32_t sbase, const float* __restrict__ A, const __half* __restrict__ B1,
    int m0, int n0, int kt, int tid)
{
    const int k0 = kt * BK;
    // B tile: async copies first (independent of A stalls)
#pragma unroll
    for (int i = 0; i < 4; i++) {
        int id = tid + 256 * i;
        int r = id >> 3, c = id & 7;
        uint32_t soff = r * 128 + ((c ^ (r & 7)) << 4);
        cpasync16(sbase + 16384 + soff, B1 + (size_t)(n0 + r) * KDIM + k0 + c * 8);
    }
    // A tile: fp32 LDG -> cvt -> fp16 STS at the same swizzled layout.
    // Issue all LDGs up front (MLP 8) then convert/store.
    float4 v[4][2];
#pragma unroll
    for (int i = 0; i < 4; i++) {
        int id = tid + 256 * i;
        int r = id >> 3, c = id & 7;
        const float* ga = A + (size_t)(m0 + r) * KDIM + k0 + c * 8;
        v[i][0] = __ldg((const float4*)ga);
        v[i][1] = __ldg((const float4*)(ga + 4));
    }
#pragma unroll
    for (int i = 0; i < 4; i++) {
        int id = tid + 256 * i;
        int r = id >> 3, c = id & 7;
        uint32_t soff = r * 128 + ((c ^ (r & 7)) << 4);
        uint32_t h0 = pack_h2(v[i][0].x, v[i][0].y);
        uint32_t h1 = pack_h2(v[i][0].z, v[i][0].w);
        uint32_t h2 = pack_h2(v[i][1].x, v[i][1].y);
        uint32_t h3 = pack_h2(v[i][1].z, v[i][1].w);
        asm volatile("st.shared.v4.b32 [%0], {%1,%2,%3,%4};"
            :: "r"(sbase + soff), "r"(h0), "r"(h1), "r"(h2), "r"(h3) : "memory");
    }
}

template<bool SPLIT, bool AF32>
__global__ __launch_bounds__(256, 2) void mma_gemm(
    const void* __restrict__ Av, const __half* __restrict__ B1,
    const float* __restrict__ bias, void* __restrict__ Cv, int ldc)
{
    extern __shared__ char sm[];
    const uint32_t sb = smem_u32(sm);
    const int tid  = threadIdx.x;
    const int lane = tid & 31;
    const int wid  = tid >> 5;
    const int wm   = wid & 1;
    const int wn   = wid >> 1;
    const int m0 = blockIdx.y * BM;
    const int n0 = blockIdx.x * BN;

    const int lrow  = lane & 15;
    const int lhalf = lane >> 4;
    const int xorv  = lrow & 7;

    uint32_t arow[4], brow[2];
#pragma unroll
    for (int mt = 0; mt < 4; mt++) arow[mt] = (wm * 64 + mt * 16 + lrow) * 128;
#pragma unroll
    for (int nt2 = 0; nt2 < 2; nt2++)
        brow[nt2] = 16384u + (wn * 32 + nt2 * 16 + lrow) * 128;

    float acc[4][4][4];
#pragma unroll
    for (int i = 0; i < 4; i++)
#pragma unroll
        for (int j = 0; j < 4; j++)
#pragma unroll
            for (int q = 0; q < 4; q++) acc[i][j][q] = 0.f;

#define LOAD_STAGE(base, kt)                                                  \
    do {                                                                      \
        if (AF32) gemm_load_stage_f32(base, (const float*)Av, B1, m0, n0, kt, tid); \
        else      gemm_load_stage_h(base, (const __half*)Av, B1, m0, n0, kt, tid);  \
    } while (0)

    LOAD_STAGE(sb,             0); CP_COMMIT();
    LOAD_STAGE(sb + STG_BYTES, 1); CP_COMMIT();

    for (int kt = 0; kt < NK; kt++) {
        if (kt < NK - 2) {
            LOAD_STAGE(sb + ((kt + 2) % NSTAGE) * STG_BYTES, kt + 2);
            CP_COMMIT();
            asm volatile("cp.async.wait_group 2;" ::: "memory");
        } else if (kt == NK - 2) {
            asm volatile("cp.async.wait_group 1;" ::: "memory");
        } else {
            asm volatile("cp.async.wait_group 0;" ::: "memory");
        }
        __syncthreads();

        const uint32_t st = sb + (kt % NSTAGE) * STG_BYTES;
#pragma unroll
        for (int ks = 0; ks < 4; ks++) {
            const uint32_t coff = (uint32_t)(((ks * 2 + lhalf) ^ xorv) << 4);
            uint32_t ah[4][4], bh[2][4];
#pragma unroll
            for (int mt = 0; mt < 4; mt++) ldsm4(ah[mt], st + arow[mt] + coff);
#pragma unroll
            for (int nt2 = 0; nt2 < 2; nt2++) ldsm4(bh[nt2], st + brow[nt2] + coff);
#pragma unroll
            for (int mt = 0; mt < 4; mt++)
#pragma unroll
                for (int nt = 0; nt < 4; nt++) {
                    const int n2 = nt >> 1, sel = nt & 1;
                    mma16816(acc[mt][nt], ah[mt], bh[n2][sel], bh[n2][sel + 2]);
                }
        }
        __syncthreads();
    }
#undef LOAD_STAGE

#pragma unroll
    for (int nt = 0; nt < 4; nt++) {
        const int col = n0 + wn * 32 + nt * 8 + (lane & 3) * 2;
        const float bx = __ldg(bias + col);
        const float by = __ldg(bias + col + 1);
#pragma unroll
        for (int mt = 0; mt < 4; mt++) {
            const int row = m0 + wm * 64 + mt * 16 + (lane >> 2);
            if (SPLIT) {
                __half* Cb = (__half*)Cv;
                *(uint32_t*)(Cb + (size_t)row * ldc + col) =
                    pack_h2(acc[mt][nt][0] + bx, acc[mt][nt][1] + by);
                *(uint32_t*)(Cb + (size_t)(row + 8) * ldc + col) =
                    pack_h2(acc[mt][nt][2] + bx, acc[mt][nt][3] + by);
            } else {
                float* C = (float*)Cv;
                float2 v0 = make_float2(acc[mt][nt][0] + bx, acc[mt][nt][1] + by);
                float2 v1 = make_float2(acc[mt][nt][2] + bx, acc[mt][nt][3] + by);
                *(float2*)(C + (size_t)row * ldc + col)       = v0;
                *(float2*)(C + (size_t)(row + 8) * ldc + col) = v1;
            }
        }
    }
}

// ---------------------------------------------------------------------------
// Tensor-core flash attention, all-fp16 operands -- exact R13 form.
// Per CTA: 128 q-rows, one (b,h). 8 warps x 16 rows. Key tiles of 64.
// smem: Q 16K | 2 stages of {K 8K | V 8K} = 48KB -> 2 CTAs/SM.
// qkv1 row layout: [q(1024) k(1024) v(1024)], row stride 3072.
// ---------------------------------------------------------------------------
#define AT_SMEM (16384 + 2 * 16384)   /* 49152 */
#define C1 0.18033688f                /* 0.125 * log2(e) */

__device__ __forceinline__ void attn_load_kv(
    uint32_t stage, const __half* __restrict__ kvb, int tid)
{
#pragma unroll
    for (int i = 0; i < 2; i++) {
        int id = tid + 256 * i;            // 0..511 -> 64 rows x 8 chunks
        int r = id >> 3, c = id & 7;
        uint32_t soff = r * 128 + ((c ^ (r & 7)) << 4);
        const __half* g = kvb + (size_t)r * 3072 + c * 8;
        cpasync16(stage +        soff, g + 1024);   // K
        cpasync16(stage + 8192 + soff, g + 2048);   // V
    }
}

__global__ __launch_bounds__(256, 2) void attn_mma(
    const __half* __restrict__ qkv1, __half* __restrict__ att1)
{
    extern __shared__ char sm[];
    const uint32_t sb = smem_u32(sm);
    const uint32_t Qs = sb, ST0 = sb + 16384;

    const int tid = threadIdx.x, lane = tid & 31, wid = tid >> 5;
    const int qb = blockIdx.x, h = blockIdx.y, b = blockIdx.z;
    const int lrow = lane & 15, lhalf = lane >> 4;
    const size_t rowbase = (size_t)b * SEQ;
    const __half* qg  = qkv1 + (rowbase + qb * 128) * 3072 + h * 64;
    const __half* kvg = qkv1 + rowbase * 3072 + h * 64;

    // Q tile load
#pragma unroll
    for (int i = 0; i < 4; i++) {
        int id = tid + 256 * i;            // 0..1023 -> 128 rows x 8 chunks
        int r = id >> 3, c = id & 7;
        uint32_t soff = r * 128 + ((c ^ (r & 7)) << 4);
        cpasync16(Qs + soff, qg + (size_t)r * 3072 + c * 8);
    }
    CP_COMMIT();
    attn_load_kv(ST0,         kvg,             tid); CP_COMMIT();
    attn_load_kv(ST0 + 16384, kvg + 64 * 3072, tid); CP_COMMIT();

    // Q fragments to registers
    asm volatile("cp.async.wait_group 2;" ::: "memory");
    __syncthreads();
    uint32_t qf[4][4];
    {
        int r = wid * 16 + lrow;
        uint32_t ro = (uint32_t)r * 128;
        int xv = r & 7;
#pragma unroll
        for (int ds = 0; ds < 4; ds++) {
            uint32_t co = (uint32_t)(((ds * 2 + lhalf) ^ xv) << 4);
            ldsm4(qf[ds], Qs + ro + co);
        }
    }

    float oacc[8][4];
#pragma unroll
    for (int t = 0; t < 8; t++)
#pragma unroll
        for (int q = 0; q < 4; q++) oacc[t][q] = 0.f;
    float m0 = -1e30f, m1 = -1e30f, l0 = 0.f, l1 = 0.f;

    const int kxv = lrow & 7;
    for (int kt = 0; kt < 32; kt++) {
        if (kt == 31) asm volatile("cp.async.wait_group 0;" ::: "memory");
        else          asm volatile("cp.async.wait_group 1;" ::: "memory");
        __syncthreads();
        const uint32_t st = ST0 + (uint32_t)(kt & 1) * 16384;

        // ---- S = Q K^T
        float sacc[8][4];
#pragma unroll
        for (int t = 0; t < 8; t++)
#pragma unroll
            for (int q = 0; q < 4; q++) sacc[t][q] = 0.f;

#pragma unroll
        for (int ds = 0; ds < 4; ds++) {
            uint32_t kh[4][4];
            const uint32_t co = (uint32_t)(((ds * 2 + lhalf) ^ kxv) << 4);
#pragma unroll
            for (int g = 0; g < 4; g++)
                ldsm4(kh[g], st + (uint32_t)(g * 16 + lrow) * 128 + co);
#pragma unroll
            for (int g = 0; g < 4; g++)
#pragma unroll
                for (int sel = 0; sel < 2; sel++)
                    mma16816(sacc[g * 2 + sel], qf[ds], kh[g][sel], kh[g][sel + 2]);
        }

        // ---- online softmax
        float mx0 = sacc[0][0], mx1 = sacc[0][2];
#pragma unroll
        for (int t = 0; t < 8; t++) {
            mx0 = fmaxf(mx0, fmaxf(sacc[t][0], sacc[t][1]));
            mx1 = fmaxf(mx1, fmaxf(sacc[t][2], sacc[t][3]));
        }
        mx0 = fmaxf(mx0, __shfl_xor_sync(0xffffffffu, mx0, 1));
        mx0 = fmaxf(mx0, __shfl_xor_sync(0xffffffffu, mx0, 2));
        mx1 = fmaxf(mx1, __shfl_xor_sync(0xffffffffu, mx1, 1));
        mx1 = fmaxf(mx1, __shfl_xor_sync(0xffffffffu, mx1, 2));
        const float mn0 = fmaxf(m0, mx0), mn1 = fmaxf(m1, mx1);
        const float a0 = ex2((m0 - mn0) * C1), a1 = ex2((m1 - mn1) * C1);
        const float mc0 = mn0 * C1, mc1 = mn1 * C1;
        float ls0 = 0.f, ls1 = 0.f;
#pragma unroll
        for (int t = 0; t < 8; t++) {
            sacc[t][0] = ex2(fmaf(sacc[t][0], C1, -mc0));
            sacc[t][1] = ex2(fmaf(sacc[t][1], C1, -mc0));
            sacc[t][2] = ex2(fmaf(sacc[t][2], C1, -mc1));
            sacc[t][3] = ex2(fmaf(sacc[t][3], C1, -mc1));
            ls0 += sacc[t][0] + sacc[t][1];
            ls1 += sacc[t][2] + sacc[t][3];
        }
        ls0 += __shfl_xor_sync(0xffffffffu, ls0, 1);
        ls0 += __shfl_xor_sync(0xffffffffu, ls0, 2);
        ls1 += __shfl_xor_sync(0xffffffffu, ls1, 1);
        ls1 += __shfl_xor_sync(0xffffffffu, ls1, 2);
        m0 = mn0; m1 = mn1;
        l0 = l0 * a0 + ls0; l1 = l1 * a1 + ls1;
#pragma unroll
        for (int t = 0; t < 8; t++) {
            oacc[t][0] *= a0; oacc[t][1] *= a0;
            oacc[t][2] *= a1; oacc[t][3] *= a1;
        }

        // ---- O += P V
#pragma unroll
        for (int kg = 0; kg < 4; kg++) {
            uint32_t aph[4];
            {
                const float* t0 = sacc[2 * kg];
                const float* t1 = sacc[2 * kg + 1];
                aph[0] = pack_h2(t0[0], t0[1]);
                aph[1] = pack_h2(t0[2], t0[3]);
                aph[2] = pack_h2(t1[0], t1[1]);
                aph[3] = pack_h2(t1[2], t1[3]);
            }
            const uint32_t vro = st + 8192 + (uint32_t)(kg * 16 + lrow) * 128;
#pragma unroll
            for (int dg = 0; dg < 4; dg++) {
                uint32_t vh[4];
                ldsm4t(vh, vro + (uint32_t)(((dg * 2 + lhalf) ^ kxv) << 4));
#pragma unroll
                for (int sel = 0; sel < 2; sel++)
                    mma16816(oacc[dg * 2 + sel], aph, vh[2 * sel], vh[2 * sel + 1]);
            }
        }
        __syncthreads();
        if (kt + 2 < 32) {
            attn_load_kv(ST0 + (uint32_t)(kt & 1) * 16384,
                         kvg + (size_t)(kt + 2) * 64 * 3072, tid);
            CP_COMMIT();
        }
    }

    // ---- epilogue
    const float inv0 = 1.0f / l0, inv1 = 1.0f / l1;
    const size_t grow = rowbase + (size_t)qb * 128 + wid * 16 + (lane >> 2);
#pragma unroll
    for (int t = 0; t < 8; t++) {
        const int col = h * 64 + t * 8 + (lane & 3) * 2;
        *(uint32_t*)(att1 + grow * 1024 + col) =
            pack_h2(oacc[t][0] * inv0, oacc[t][1] * inv0);
        *(uint32_t*)(att1 + (grow + 8) * 1024 + col) =
            pack_h2(oacc[t][2] * inv1, oacc[t][3] * inv1);
    }
}

// ---------------------------------------------------------------------------
// Host side
// ---------------------------------------------------------------------------
extern "C" void kernel_launch(void* const* d_in, const int* in_sizes, int n_in,
                              void* d_out, int out_size)
{
    (void)in_sizes; (void)n_in; (void)out_size;
    const float* x     = (const float*)d_in[0];
    const float* w_qkv = (const float*)d_in[1];
    const float* b_qkv = (const float*)d_in[2];
    const float* w_out = (const float*)d_in[3];
    const float* b_out = (const float*)d_in[4];
    float* out = (float*)d_out;

    __half *qkv1, *att1, *wq2, *wo2;
    cudaGetSymbolAddress((void**)&qkv1, g_qkv1);
    cudaGetSymbolAddress((void**)&att1, g_att1);
    cudaGetSymbolAddress((void**)&wq2,  g_wq2);
    cudaGetSymbolAddress((void**)&wo2,  g_wo2);

    cudaFuncSetAttribute((const void*)mma_gemm<true, true>,
                         cudaFuncAttributeMaxDynamicSharedMemorySize, GEMM_SMEM);
    cudaFuncSetAttribute((const void*)mma_gemm<false, false>,
                         cudaFuncAttributeMaxDynamicSharedMemorySize, GEMM_SMEM);
    cudaFuncSetAttribute((const void*)attn_mma,
                         cudaFuncAttributeMaxDynamicSharedMemorySize, AT_SMEM);

    // 1) operand prep (weights only; x cast fused into GEMM1)
    prep_w<<<PREP_BLOCKS, 256>>>(w_qkv, wq2, w_out, wo2);

    // 2) QKV projection (A = fp32 x, inline cast) -> fp16 qkv
    mma_gemm<true, true><<<dim3(QKVN / BN, MROWS / BM), 256, GEMM_SMEM>>>(
        x, wq2, b_qkv, qkv1, QKVN);

    // 3) tensor-core flash attention -> fp16 att
    attn_mma<<<dim3(SEQ / 128, NHEAD, BATCH), 256, AT_SMEM>>>(qkv1, att1);

    // 4) output projection -> fp32 out
    mma_gemm<false, false><<<dim3(EMBED / BN, MROWS / BM), 256, GEMM_SMEM>>>(
        att1, wo2, b_out, out, EMBED);
}

// round 15
// speedup vs baseline: 1.0848x; 1.0848x over previous
#include <cuda_runtime.h>
#include <cuda_fp16.h>
#include <cstdint>

#define EMBED   1024
#define NHEAD   16
#define HD      64
#define SEQ     2048
#define BATCH   4
#define MROWS   (BATCH * SEQ)      /* 8192 */
#define QKVN    (3 * EMBED)        /* 3072 */
#define KDIM    1024

// ---------------------------------------------------------------------------
// Scratch (device globals -- runtime allocation is forbidden)
// ---------------------------------------------------------------------------
static __device__ __half g_x1  [(size_t)MROWS * KDIM];       // x fp16
static __device__ __half g_qkv1[(size_t)MROWS * QKVN];       // qkv fp16
static __device__ __half g_att1[(size_t)MROWS * KDIM];       // attn out fp16
static __device__ __half g_wq2 [(size_t)QKVN  * KDIM];       // w_qkv^T fp16
static __device__ __half g_wo2 [(size_t)EMBED * KDIM];       // w_out^T fp16

// ---------------------------------------------------------------------------
// PTX helpers (baseline ISA, sm_80-compatible encodings only)
// ---------------------------------------------------------------------------
__device__ __forceinline__ uint32_t smem_u32(const void* p) {
    uint32_t a;
    asm("{ .reg .u64 t; cvta.to.shared.u64 t, %1; cvt.u32.u64 %0, t; }"
        : "=r"(a) : "l"(p));
    return a;
}
__device__ __forceinline__ void cpasync16(uint32_t dst, const void* src) {
    asm volatile("cp.async.cg.shared.global [%0], [%1], 16;"
        :: "r"(dst), "l"(src) : "memory");
}
#define CP_COMMIT() asm volatile("cp.async.commit_group;" ::: "memory")

__device__ __forceinline__ void ldsm4(uint32_t* r, uint32_t addr) {
    asm volatile("ldmatrix.sync.aligned.m8n8.x4.shared.b16 {%0,%1,%2,%3}, [%4];"
        : "=r"(r[0]), "=r"(r[1]), "=r"(r[2]), "=r"(r[3]) : "r"(addr));
}
__device__ __forceinline__ void ldsm4t(uint32_t* r, uint32_t addr) {
    asm volatile("ldmatrix.sync.aligned.m8n8.x4.trans.shared.b16 {%0,%1,%2,%3}, [%4];"
        : "=r"(r[0]), "=r"(r[1]), "=r"(r[2]), "=r"(r[3]) : "r"(addr));
}
// fp16 MMA, fp32 accumulate
__device__ __forceinline__ void mma16816(float* c, const uint32_t* a,
                                         uint32_t b0, uint32_t b1) {
    asm volatile(
        "mma.sync.aligned.m16n8k16.row.col.f32.f16.f16.f32 "
        "{%0,%1,%2,%3}, {%4,%5,%6,%7}, {%8,%9}, {%0,%1,%2,%3};"
        : "+f"(c[0]), "+f"(c[1]), "+f"(c[2]), "+f"(c[3])
        : "r"(a[0]), "r"(a[1]), "r"(a[2]), "r"(a[3]), "r"(b0), "r"(b1));
}
__device__ __forceinline__ float ex2(float x) {
    float y; asm("ex2.approx.f32 %0, %1;" : "=f"(y) : "f"(x)); return y;
}
__device__ __forceinline__ uint32_t pack_h2(float x, float y) {
    __half2 h = __floats2half2_rn(x, y);
    return *(uint32_t*)&h;
}

// ---------------------------------------------------------------------------
// operand prep: single fused kernel (R13 form).
// blocks [0, 8192)      : x fp32 -> fp16 (rowwise cast)
// blocks [8192, 11264)  : w_qkv transpose+cast (96 x 32 tiles)
// blocks [11264, 12288) : w_out transpose+cast (32 x 32 tiles)
// ---------------------------------------------------------------------------
#define NB_CAST 8192
#define NB_WQ   3072
#define PREP_BLOCKS (NB_CAST + NB_WQ + 1024)

__device__ __forceinline__ void transpose_tile(
    const float* __restrict__ w, __half* __restrict__ out, int N,
    int n0, int k0, float (*t)[33], int tid)
{
    const int tx = tid & 31, ty = tid >> 5;
#pragma unroll
    for (int i = 0; i < 4; i++)
        t[ty + 8 * i][tx] = w[(size_t)(k0 + ty + 8 * i) * N + n0 + tx];
    __syncthreads();
#pragma unroll
    for (int i = 0; i < 4; i++) {
        int nl = ty + 8 * i;
        out[(size_t)(n0 + nl) * KDIM + k0 + tx] = __float2half_rn(t[tx][nl]);
    }
}

__global__ __launch_bounds__(256) void prep_all(
    const float* __restrict__ x,     __half* __restrict__ x1,
    const float* __restrict__ wq,    __half* __restrict__ wq2,
    const float* __restrict__ wo,    __half* __restrict__ wo2)
{
    __shared__ float t[32][33];
    const int b = blockIdx.x, tid = threadIdx.x;
    if (b < NB_CAST) {
        size_t i4 = (size_t)b * 256 + tid;
        float4 v = *(const float4*)(x + i4 * 4);
        *(__half2*)(x1 + i4 * 4)     = __floats2half2_rn(v.x, v.y);
        *(__half2*)(x1 + i4 * 4 + 2) = __floats2half2_rn(v.z, v.w);
    } else if (b < NB_CAST + NB_WQ) {
        int bb = b - NB_CAST;
        transpose_tile(wq, wq2, QKVN, (bb % 96) * 32, (bb / 96) * 32, t, tid);
    } else {
        int bb = b - NB_CAST - NB_WQ;
        transpose_tile(wo, wo2, EMBED, (bb % 32) * 32, (bb / 32) * 32, t, tid);
    }
}

// ---------------------------------------------------------------------------
// mma.sync fp16 GEMM -- exact R10/R13 form (2 CTAs/SM, plain fragment loads).
// CTA 128x128, warp tile 64x32 (2Mx4N), BK=64, 3-stage cp.async (32KB/stage).
// SPLIT=true : C fp16 [M,ldc] + bias.   SPLIT=false: C fp32 [M,ldc] + bias.
// ---------------------------------------------------------------------------
#define BM 128
#define BN 128
#define BK 64
#define NK (KDIM / BK)            /* 16 */
#define NSTAGE 3
#define STG_BYTES 32768
#define GEMM_SMEM (NSTAGE * STG_BYTES)   /* 98304 */

__device__ __forceinline__ void gemm_load_stage(
    uint32_t sbase, const __half* __restrict__ A, const __half* __restrict__ B1,
    int m0, int n0, int kt, int tid)
{
    const int k0 = kt * BK;
#pragma unroll
    for (int i = 0; i < 4; i++) {
        int id = tid + 256 * i;            // 0..1023: 128 rows x 8 chunks
        int r = id >> 3;
        int c = id & 7;
        uint32_t soff = r * 128 + ((c ^ (r & 7)) << 4);
        cpasync16(sbase + soff,         A  + (size_t)(m0 + r) * KDIM + k0 + c * 8);
        cpasync16(sbase + 16384 + soff, B1 + (size_t)(n0 + r) * KDIM + k0 + c * 8);
    }
}

template<bool SPLIT>
__global__ __launch_bounds__(256, 2) void mma_gemm(
    const __half* __restrict__ A, const __half* __restrict__ B1,
    const float* __restrict__ bias, void* __restrict__ Cv, int ldc)
{
    extern __shared__ char sm[];
    const uint32_t sb = smem_u32(sm);
    const int tid  = threadIdx.x;
    const int lane = tid & 31;
    const int wid  = tid >> 5;
    const int wm   = wid & 1;
    const int wn   = wid >> 1;
    const int m0 = blockIdx.y * BM;
    const int n0 = blockIdx.x * BN;

    const int lrow  = lane & 15;
    const int lhalf = lane >> 4;
    const int xorv  = lrow & 7;

    uint32_t arow[4], brow[2];
#pragma unroll
    for (int mt = 0; mt < 4; mt++) arow[mt] = (wm * 64 + mt * 16 + lrow) * 128;
#pragma unroll
    for (int nt2 = 0; nt2 < 2; nt2++)
        brow[nt2] = 16384u + (wn * 32 + nt2 * 16 + lrow) * 128;

    float acc[4][4][4];
#pragma unroll
    for (int i = 0; i < 4; i++)
#pragma unroll
        for (int j = 0; j < 4; j++)
#pragma unroll
            for (int q = 0; q < 4; q++) acc[i][j][q] = 0.f;

    gemm_load_stage(sb,             A, B1, m0, n0, 0, tid); CP_COMMIT();
    gemm_load_stage(sb + STG_BYTES, A, B1, m0, n0, 1, tid); CP_COMMIT();

    for (int kt = 0; kt < NK; kt++) {
        if (kt < NK - 2) {
            gemm_load_stage(sb + ((kt + 2) % NSTAGE) * STG_BYTES, A, B1, m0, n0, kt + 2, tid);
            CP_COMMIT();
            asm volatile("cp.async.wait_group 2;" ::: "memory");
        } else if (kt == NK - 2) {
            asm volatile("cp.async.wait_group 1;" ::: "memory");
        } else {
            asm volatile("cp.async.wait_group 0;" ::: "memory");
        }
        __syncthreads();

        const uint32_t st = sb + (kt % NSTAGE) * STG_BYTES;
#pragma unroll
        for (int ks = 0; ks < 4; ks++) {
            const uint32_t coff = (uint32_t)(((ks * 2 + lhalf) ^ xorv) << 4);
            uint32_t ah[4][4], bh[2][4];
#pragma unroll
            for (int mt = 0; mt < 4; mt++) ldsm4(ah[mt], st + arow[mt] + coff);
#pragma unroll
            for (int nt2 = 0; nt2 < 2; nt2++) ldsm4(bh[nt2], st + brow[nt2] + coff);
#pragma unroll
            for (int mt = 0; mt < 4; mt++)
#pragma unroll
                for (int nt = 0; nt < 4; nt++) {
                    const int n2 = nt >> 1, sel = nt & 1;
                    mma16816(acc[mt][nt], ah[mt], bh[n2][sel], bh[n2][sel + 2]);
                }
        }
        __syncthreads();
    }

#pragma unroll
    for (int nt = 0; nt < 4; nt++) {
        const int col = n0 + wn * 32 + nt * 8 + (lane & 3) * 2;
        const float bx = __ldg(bias + col);
        const float by = __ldg(bias + col + 1);
#pragma unroll
        for (int mt = 0; mt < 4; mt++) {
            const int row = m0 + wm * 64 + mt * 16 + (lane >> 2);
            if (SPLIT) {
                __half* Cb = (__half*)Cv;
                *(uint32_t*)(Cb + (size_t)row * ldc + col) =
                    pack_h2(acc[mt][nt][0] + bx, acc[mt][nt][1] + by);
                *(uint32_t*)(Cb + (size_t)(row + 8) * ldc + col) =
                    pack_h2(acc[mt][nt][2] + bx, acc[mt][nt][3] + by);
            } else {
                float* C = (float*)Cv;
                float2 v0 = make_float2(acc[mt][nt][0] + bx, acc[mt][nt][1] + by);
                float2 v1 = make_float2(acc[mt][nt][2] + bx, acc[mt][nt][3] + by);
                *(float2*)(C + (size_t)row * ldc + col)       = v0;
                *(float2*)(C + (size_t)(row + 8) * ldc + col) = v1;
            }
        }
    }
}

// ---------------------------------------------------------------------------
// Tensor-core flash attention, all-fp16 operands. R13 form with KV pipeline
// deepened to 3 stages (prefetch distance 3; wait_group 2 steady state).
// Per CTA: 128 q-rows, one (b,h). 8 warps x 16 rows. Key tiles of 64.
// smem: Q 16K | 3 stages of {K 8K | V 8K} = 64KB -> 2 CTAs/SM (128KB/SM).
// qkv1 row layout: [q(1024) k(1024) v(1024)], row stride 3072.
// ---------------------------------------------------------------------------
#define AT_SMEM (16384 + 3 * 16384)   /* 65536 */
#define C1 0.18033688f                /* 0.125 * log2(e) */

__device__ __forceinline__ void attn_load_kv(
    uint32_t stage, const __half* __restrict__ kvb, int tid)
{
#pragma unroll
    for (int i = 0; i < 2; i++) {
        int id = tid + 256 * i;            // 0..511 -> 64 rows x 8 chunks
        int r = id >> 3, c = id & 7;
        uint32_t soff = r * 128 + ((c ^ (r & 7)) << 4);
        const __half* g = kvb + (size_t)r * 3072 + c * 8;
        cpasync16(stage +        soff, g + 1024);   // K
        cpasync16(stage + 8192 + soff, g + 2048);   // V
    }
}

__global__ __launch_bounds__(256, 2) void attn_mma(
    const __half* __restrict__ qkv1, __half* __restrict__ att1)
{
    extern __shared__ char sm[];
    const uint32_t sb = smem_u32(sm);
    const uint32_t Qs = sb, ST0 = sb + 16384;

    const int tid = threadIdx.x, lane = tid & 31, wid = tid >> 5;
    const int qb = blockIdx.x, h = blockIdx.y, b = blockIdx.z;
    const int lrow = lane & 15, lhalf = lane >> 4;
    const size_t rowbase = (size_t)b * SEQ;
    const __half* qg  = qkv1 + (rowbase + qb * 128) * 3072 + h * 64;
    const __half* kvg = qkv1 + rowbase * 3072 + h * 64;

    // Q tile load (bundled with first KV group)
#pragma unroll
    for (int i = 0; i < 4; i++) {
        int id = tid + 256 * i;            // 0..1023 -> 128 rows x 8 chunks
        int r = id >> 3, c = id & 7;
        uint32_t soff = r * 128 + ((c ^ (r & 7)) << 4);
        cpasync16(Qs + soff, qg + (size_t)r * 3072 + c * 8);
    }
    attn_load_kv(ST0,             kvg,              tid); CP_COMMIT();
    attn_load_kv(ST0 + 16384,     kvg +  64 * 3072, tid); CP_COMMIT();
    attn_load_kv(ST0 + 2 * 16384, kvg + 128 * 3072, tid); CP_COMMIT();

    // Q fragments to registers (group 0 complete when <=2 groups outstanding)
    asm volatile("cp.async.wait_group 2;" ::: "memory");
    __syncthreads();
    uint32_t qf[4][4];
    {
        int r = wid * 16 + lrow;
        uint32_t ro = (uint32_t)r * 128;
        int xv = r & 7;
#pragma unroll
        for (int ds = 0; ds < 4; ds++) {
            uint32_t co = (uint32_t)(((ds * 2 + lhalf) ^ xv) << 4);
            ldsm4(qf[ds], Qs + ro + co);
        }
    }

    float oacc[8][4];
#pragma unroll
    for (int t = 0; t < 8; t++)
#pragma unroll
        for (int q = 0; q < 4; q++) oacc[t][q] = 0.f;
    float m0 = -1e30f, m1 = -1e30f, l0 = 0.f, l1 = 0.f;

    const int kxv = lrow & 7;
    for (int kt = 0; kt < 32; kt++) {
        // buffers hold kt, kt+1, kt+2(loading); tile kt ready when the
        // two newer groups may remain outstanding.
        if (kt <= 29)      asm volatile("cp.async.wait_group 2;" ::: "memory");
        else if (kt == 30) asm volatile("cp.async.wait_group 1;" ::: "memory");
        else               asm volatile("cp.async.wait_group 0;" ::: "memory");
        __syncthreads();
        const uint32_t st = ST0 + (uint32_t)(kt % 3) * 16384;

        // ---- S = Q K^T
        float sacc[8][4];
#pragma unroll
        for (int t = 0; t < 8; t++)
#pragma unroll
            for (int q = 0; q < 4; q++) sacc[t][q] = 0.f;

#pragma unroll
        for (int ds = 0; ds < 4; ds++) {
            uint32_t kh[4][4];
            const uint32_t co = (uint32_t)(((ds * 2 + lhalf) ^ kxv) << 4);
#pragma unroll
            for (int g = 0; g < 4; g++)
                ldsm4(kh[g], st + (uint32_t)(g * 16 + lrow) * 128 + co);
#pragma unroll
            for (int g = 0; g < 4; g++)
#pragma unroll
                for (int sel = 0; sel < 2; sel++)
                    mma16816(sacc[g * 2 + sel], qf[ds], kh[g][sel], kh[g][sel + 2]);
        }

        // ---- online softmax
        float mx0 = sacc[0][0], mx1 = sacc[0][2];
#pragma unroll
        for (int t = 0; t < 8; t++) {
            mx0 = fmaxf(mx0, fmaxf(sacc[t][0], sacc[t][1]));
            mx1 = fmaxf(mx1, fmaxf(sacc[t][2], sacc[t][3]));
        }
        mx0 = fmaxf(mx0, __shfl_xor_sync(0xffffffffu, mx0, 1));
        mx0 = fmaxf(mx0, __shfl_xor_sync(0xffffffffu, mx0, 2));
        mx1 = fmaxf(mx1, __shfl_xor_sync(0xffffffffu, mx1, 1));
        mx1 = fmaxf(mx1, __shfl_xor_sync(0xffffffffu, mx1, 2));
        const float mn0 = fmaxf(m0, mx0), mn1 = fmaxf(m1, mx1);
        const float a0 = ex2((m0 - mn0) * C1), a1 = ex2((m1 - mn1) * C1);
        const float mc0 = mn0 * C1, mc1 = mn1 * C1;
        float ls0 = 0.f, ls1 = 0.f;
#pragma unroll
        for (int t = 0; t < 8; t++) {
            sacc[t][0] = ex2(fmaf(sacc[t][0], C1, -mc0));
            sacc[t][1] = ex2(fmaf(sacc[t][1], C1, -mc0));
            sacc[t][2] = ex2(fmaf(sacc[t][2], C1, -mc1));
            sacc[t][3] = ex2(fmaf(sacc[t][3], C1, -mc1));
            ls0 += sacc[t][0] + sacc[t][1];
            ls1 += sacc[t][2] + sacc[t][3];
        }
        ls0 += __shfl_xor_sync(0xffffffffu, ls0, 1);
        ls0 += __shfl_xor_sync(0xffffffffu, ls0, 2);
        ls1 += __shfl_xor_sync(0xffffffffu, ls1, 1);
        ls1 += __shfl_xor_sync(0xffffffffu, ls1, 2);
        m0 = mn0; m1 = mn1;
        l0 = l0 * a0 + ls0; l1 = l1 * a1 + ls1;
#pragma unroll
        for (int t = 0; t < 8; t++) {
            oacc[t][0] *= a0; oacc[t][1] *= a0;
            oacc[t][2] *= a1; oacc[t][3] *= a1;
        }

        // ---- O += P V
#pragma unroll
        for (int kg = 0; kg < 4; kg++) {
            uint32_t aph[4];
            {
                const float* t0 = sacc[2 * kg];
                const float* t1 = sacc[2 * kg + 1];
                aph[0] = pack_h2(t0[0], t0[1]);
                aph[1] = pack_h2(t0[2], t0[3]);
                aph[2] = pack_h2(t1[0], t1[1]);
                aph[3] = pack_h2(t1[2], t1[3]);
            }
            const uint32_t vro = st + 8192 + (uint32_t)(kg * 16 + lrow) * 128;
#pragma unroll
            for (int dg = 0; dg < 4; dg++) {
                uint32_t vh[4];
                ldsm4t(vh, vro + (uint32_t)(((dg * 2 + lhalf) ^ kxv) << 4));
#pragma unroll
                for (int sel = 0; sel < 2; sel++)
                    mma16816(oacc[dg * 2 + sel], aph, vh[2 * sel], vh[2 * sel + 1]);
            }
        }
        __syncthreads();
        if (kt + 3 < 32) {
            attn_load_kv(ST0 + (uint32_t)(kt % 3) * 16384,
                         kvg + (size_t)(kt + 3) * 64 * 3072, tid);
            CP_COMMIT();
        }
    }

    // ---- epilogue
    const float inv0 = 1.0f / l0, inv1 = 1.0f / l1;
    const size_t grow = rowbase + (size_t)qb * 128 + wid * 16 + (lane >> 2);
#pragma unroll
    for (int t = 0; t < 8; t++) {
        const int col = h * 64 + t * 8 + (lane & 3) * 2;
        *(uint32_t*)(att1 + grow * 1024 + col) =
            pack_h2(oacc[t][0] * inv0, oacc[t][1] * inv0);
        *(uint32_t*)(att1 + (grow + 8) * 1024 + col) =
            pack_h2(oacc[t][2] * inv1, oacc[t][3] * inv1);
    }
}

// ---------------------------------------------------------------------------
// Host side
// ---------------------------------------------------------------------------
extern "C" void kernel_launch(void* const* d_in, const int* in_sizes, int n_in,
                              void* d_out, int out_size)
{
    (void)in_sizes; (void)n_in; (void)out_size;
    const float* x     = (const float*)d_in[0];
    const float* w_qkv = (const float*)d_in[1];
    const float* b_qkv = (const float*)d_in[2];
    const float* w_out = (const float*)d_in[3];
    const float* b_out = (const float*)d_in[4];
    float* out = (float*)d_out;

    __half *x1, *qkv1, *att1, *wq2, *wo2;
    cudaGetSymbolAddress((void**)&x1,   g_x1);
    cudaGetSymbolAddress((void**)&qkv1, g_qkv1);
    cudaGetSymbolAddress((void**)&att1, g_att1);
    cudaGetSymbolAddress((void**)&wq2,  g_wq2);
    cudaGetSymbolAddress((void**)&wo2,  g_wo2);

    cudaFuncSetAttribute(mma_gemm<true>,
                         cudaFuncAttributeMaxDynamicSharedMemorySize, GEMM_SMEM);
    cudaFuncSetAttribute(mma_gemm<false>,
                         cudaFuncAttributeMaxDynamicSharedMemorySize, GEMM_SMEM);
    cudaFuncSetAttribute(attn_mma, cudaFuncAttributeMaxDynamicSharedMemorySize, AT_SMEM);

    // 1) operand prep (single fused launch)
    prep_all<<<PREP_BLOCKS, 256>>>(x, x1, w_qkv, wq2, w_out, wo2);

    // 2) QKV projection -> fp16 qkv
    mma_gemm<true><<<dim3(QKVN / BN, MROWS / BM), 256, GEMM_SMEM>>>(
        x1, wq2, b_qkv, qkv1, QKVN);

    // 3) tensor-core flash attention -> fp16 att
    attn_mma<<<dim3(SEQ / 128, NHEAD, BATCH), 256, AT_SMEM>>>(qkv1, att1);

    // 4) output projection -> fp32 out
    mma_gemm<false><<<dim3(EMBED / BN, MROWS / BM), 256, GEMM_SMEM>>>(
        att1, wo2, b_out, out, EMBED);
}

// round 16
// speedup vs baseline: 1.1124x; 1.0254x over previous
#include <cuda_runtime.h>
#include <cuda_fp16.h>
#include <cstdint>

#define EMBED   1024
#define NHEAD   16
#define HD      64
#define SEQ     2048
#define BATCH   4
#define MROWS   (BATCH * SEQ)      /* 8192 */
#define QKVN    (3 * EMBED)        /* 3072 */
#define KDIM    1024

// ---------------------------------------------------------------------------
// Scratch (device globals -- runtime allocation is forbidden)
// ---------------------------------------------------------------------------
static __device__ __half g_x1  [(size_t)MROWS * KDIM];       // x fp16
static __device__ __half g_qkv1[(size_t)MROWS * QKVN];       // qkv fp16
static __device__ __half g_att1[(size_t)MROWS * KDIM];       // attn out fp16
static __device__ __half g_wq2 [(size_t)QKVN  * KDIM];       // w_qkv^T fp16
static __device__ __half g_wo2 [(size_t)EMBED * KDIM];       // w_out^T fp16

// ---------------------------------------------------------------------------
// PTX helpers (baseline ISA, sm_80-compatible encodings only)
// ---------------------------------------------------------------------------
__device__ __forceinline__ uint32_t smem_u32(const void* p) {
    uint32_t a;
    asm("{ .reg .u64 t; cvta.to.shared.u64 t, %1; cvt.u32.u64 %0, t; }"
        : "=r"(a) : "l"(p));
    return a;
}
__device__ __forceinline__ void cpasync16(uint32_t dst, const void* src) {
    asm volatile("cp.async.cg.shared.global [%0], [%1], 16;"
        :: "r"(dst), "l"(src) : "memory");
}
#define CP_COMMIT() asm volatile("cp.async.commit_group;" ::: "memory")

__device__ __forceinline__ void ldsm4(uint32_t* r, uint32_t addr) {
    asm volatile("ldmatrix.sync.aligned.m8n8.x4.shared.b16 {%0,%1,%2,%3}, [%4];"
        : "=r"(r[0]), "=r"(r[1]), "=r"(r[2]), "=r"(r[3]) : "r"(addr));
}
__device__ __forceinline__ void ldsm4t(uint32_t* r, uint32_t addr) {
    asm volatile("ldmatrix.sync.aligned.m8n8.x4.trans.shared.b16 {%0,%1,%2,%3}, [%4];"
        : "=r"(r[0]), "=r"(r[1]), "=r"(r[2]), "=r"(r[3]) : "r"(addr));
}
// fp16 MMA, fp32 accumulate
__device__ __forceinline__ void mma16816(float* c, const uint32_t* a,
                                         uint32_t b0, uint32_t b1) {
    asm volatile(
        "mma.sync.aligned.m16n8k16.row.col.f32.f16.f16.f32 "
        "{%0,%1,%2,%3}, {%4,%5,%6,%7}, {%8,%9}, {%0,%1,%2,%3};"
        : "+f"(c[0]), "+f"(c[1]), "+f"(c[2]), "+f"(c[3])
        : "r"(a[0]), "r"(a[1]), "r"(a[2]), "r"(a[3]), "r"(b0), "r"(b1));
}
__device__ __forceinline__ float ex2(float x) {
    float y; asm("ex2.approx.f32 %0, %1;" : "=f"(y) : "f"(x)); return y;
}
__device__ __forceinline__ uint32_t pack_h2(float x, float y) {
    __half2 h = __floats2half2_rn(x, y);
    return *(uint32_t*)&h;
}

// ---------------------------------------------------------------------------
// operand prep: single fused kernel.
// blocks [0, 8192)      : x fp32 -> fp16 (rowwise cast)
// blocks [8192, 11264)  : w_qkv transpose+cast (96 x 32 tiles)
// blocks [11264, 12288) : w_out transpose+cast (32 x 32 tiles)
// ---------------------------------------------------------------------------
#define NB_CAST 8192
#define NB_WQ   3072
#define PREP_BLOCKS (NB_CAST + NB_WQ + 1024)

__device__ __forceinline__ void transpose_tile(
    const float* __restrict__ w, __half* __restrict__ out, int N,
    int n0, int k0, float (*t)[33], int tid)
{
    const int tx = tid & 31, ty = tid >> 5;
#pragma unroll
    for (int i = 0; i < 4; i++)
        t[ty + 8 * i][tx] = w[(size_t)(k0 + ty + 8 * i) * N + n0 + tx];
    __syncthreads();
#pragma unroll
    for (int i = 0; i < 4; i++) {
        int nl = ty + 8 * i;
        out[(size_t)(n0 + nl) * KDIM + k0 + tx] = __float2half_rn(t[tx][nl]);
    }
}

__global__ __launch_bounds__(256) void prep_all(
    const float* __restrict__ x,     __half* __restrict__ x1,
    const float* __restrict__ wq,    __half* __restrict__ wq2,
    const float* __restrict__ wo,    __half* __restrict__ wo2)
{
    __shared__ float t[32][33];
    const int b = blockIdx.x, tid = threadIdx.x;
    if (b < NB_CAST) {
        size_t i4 = (size_t)b * 256 + tid;
        float4 v = *(const float4*)(x + i4 * 4);
        *(__half2*)(x1 + i4 * 4)     = __floats2half2_rn(v.x, v.y);
        *(__half2*)(x1 + i4 * 4 + 2) = __floats2half2_rn(v.z, v.w);
    } else if (b < NB_CAST + NB_WQ) {
        int bb = b - NB_CAST;
        transpose_tile(wq, wq2, QKVN, (bb % 96) * 32, (bb / 96) * 32, t, tid);
    } else {
        int bb = b - NB_CAST - NB_WQ;
        transpose_tile(wo, wo2, EMBED, (bb % 32) * 32, (bb / 32) * 32, t, tid);
    }
}

// ---------------------------------------------------------------------------
// mma.sync fp16 GEMM (2 CTAs/SM, plain fragment loads).
// CTA 128x128, warp tile 64x32 (2Mx4N), BK=64, 3-stage cp.async (32KB/stage).
// SPLIT=true : C fp16 [M,ldc] + bias.   SPLIT=false: C fp32 [M,ldc] + bias.
// ---------------------------------------------------------------------------
#define BM 128
#define BN 128
#define BK 64
#define NK (KDIM / BK)            /* 16 */
#define NSTAGE 3
#define STG_BYTES 32768
#define GEMM_SMEM (NSTAGE * STG_BYTES)   /* 98304 */

__device__ __forceinline__ void gemm_load_stage(
    uint32_t sbase, const __half* __restrict__ A, const __half* __restrict__ B1,
    int m0, int n0, int kt, int tid)
{
    const int k0 = kt * BK;
#pragma unroll
    for (int i = 0; i < 4; i++) {
        int id = tid + 256 * i;            // 0..1023: 128 rows x 8 chunks
        int r = id >> 3;
        int c = id & 7;
        uint32_t soff = r * 128 + ((c ^ (r & 7)) << 4);
        cpasync16(sbase + soff,         A  + (size_t)(m0 + r) * KDIM + k0 + c * 8);
        cpasync16(sbase + 16384 + soff, B1 + (size_t)(n0 + r) * KDIM + k0 + c * 8);
    }
}

template<bool SPLIT>
__global__ __launch_bounds__(256, 2) void mma_gemm(
    const __half* __restrict__ A, const __half* __restrict__ B1,
    const float* __restrict__ bias, void* __restrict__ Cv, int ldc)
{
    extern __shared__ char sm[];
    const uint32_t sb = smem_u32(sm);
    const int tid  = threadIdx.x;
    const int lane = tid & 31;
    const int wid  = tid >> 5;
    const int wm   = wid & 1;
    const int wn   = wid >> 1;
    const int m0 = blockIdx.y * BM;
    const int n0 = blockIdx.x * BN;

    const int lrow  = lane & 15;
    const int lhalf = lane >> 4;
    const int xorv  = lrow & 7;

    uint32_t arow[4], brow[2];
#pragma unroll
    for (int mt = 0; mt < 4; mt++) arow[mt] = (wm * 64 + mt * 16 + lrow) * 128;
#pragma unroll
    for (int nt2 = 0; nt2 < 2; nt2++)
        brow[nt2] = 16384u + (wn * 32 + nt2 * 16 + lrow) * 128;

    float acc[4][4][4];
#pragma unroll
    for (int i = 0; i < 4; i++)
#pragma unroll
        for (int j = 0; j < 4; j++)
#pragma unroll
            for (int q = 0; q < 4; q++) acc[i][j][q] = 0.f;

    gemm_load_stage(sb,             A, B1, m0, n0, 0, tid); CP_COMMIT();
    gemm_load_stage(sb + STG_BYTES, A, B1, m0, n0, 1, tid); CP_COMMIT();

    for (int kt = 0; kt < NK; kt++) {
        if (kt < NK - 2) {
            gemm_load_stage(sb + ((kt + 2) % NSTAGE) * STG_BYTES, A, B1, m0, n0, kt + 2, tid);
            CP_COMMIT();
            asm volatile("cp.async.wait_group 2;" ::: "memory");
        } else if (kt == NK - 2) {
            asm volatile("cp.async.wait_group 1;" ::: "memory");
        } else {
            asm volatile("cp.async.wait_group 0;" ::: "memory");
        }
        __syncthreads();

        const uint32_t st = sb + (kt % NSTAGE) * STG_BYTES;
#pragma unroll
        for (int ks = 0; ks < 4; ks++) {
            const uint32_t coff = (uint32_t)(((ks * 2 + lhalf) ^ xorv) << 4);
            uint32_t ah[4][4], bh[2][4];
#pragma unroll
            for (int mt = 0; mt < 4; mt++) ldsm4(ah[mt], st + arow[mt] + coff);
#pragma unroll
            for (int nt2 = 0; nt2 < 2; nt2++) ldsm4(bh[nt2], st + brow[nt2] + coff);
#pragma unroll
            for (int mt = 0; mt < 4; mt++)
#pragma unroll
                for (int nt = 0; nt < 4; nt++) {
                    const int n2 = nt >> 1, sel = nt & 1;
                    mma16816(acc[mt][nt], ah[mt], bh[n2][sel], bh[n2][sel + 2]);
                }
        }
        __syncthreads();
    }

#pragma unroll
    for (int nt = 0; nt < 4; nt++) {
        const int col = n0 + wn * 32 + nt * 8 + (lane & 3) * 2;
        const float bx = __ldg(bias + col);
        const float by = __ldg(bias + col + 1);
#pragma unroll
        for (int mt = 0; mt < 4; mt++) {
            const int row = m0 + wm * 64 + mt * 16 + (lane >> 2);
            if (SPLIT) {
                __half* Cb = (__half*)Cv;
                *(uint32_t*)(Cb + (size_t)row * ldc + col) =
                    pack_h2(acc[mt][nt][0] + bx, acc[mt][nt][1] + by);
                *(uint32_t*)(Cb + (size_t)(row + 8) * ldc + col) =
                    pack_h2(acc[mt][nt][2] + bx, acc[mt][nt][3] + by);
            } else {
                float* C = (float*)Cv;
                float2 v0 = make_float2(acc[mt][nt][0] + bx, acc[mt][nt][1] + by);
                float2 v1 = make_float2(acc[mt][nt][2] + bx, acc[mt][nt][3] + by);
                *(float2*)(C + (size_t)row * ldc + col)       = v0;
                *(float2*)(C + (size_t)(row + 8) * ldc + col) = v1;
            }
        }
    }
}

// ---------------------------------------------------------------------------
// Tensor-core flash attention, all-fp16 operands (R13 form, depth-2 KV).
// Per CTA: 128 q-rows, one (b,h). 8 warps x 16 rows. Key tiles of 64.
// smem: Q 16K | 2 stages of {K 8K | V 8K} = 48KB -> 2 CTAs/SM.
// qkv1 row layout: [q(1024) k(1024) v(1024)], row stride 3072.
// ---------------------------------------------------------------------------
#define AT_SMEM (16384 + 2 * 16384)   /* 49152 */
#define C1 0.18033688f                /* 0.125 * log2(e) */

__device__ __forceinline__ void attn_load_kv(
    uint32_t stage, const __half* __restrict__ kvb, int tid)
{
#pragma unroll
    for (int i = 0; i < 2; i++) {
        int id = tid + 256 * i;            // 0..511 -> 64 rows x 8 chunks
        int r = id >> 3, c = id & 7;
        uint32_t soff = r * 128 + ((c ^ (r & 7)) << 4);
        const __half* g = kvb + (size_t)r * 3072 + c * 8;
        cpasync16(stage +        soff, g + 1024);   // K
        cpasync16(stage + 8192 + soff, g + 2048);   // V
    }
}

__global__ __launch_bounds__(256, 2) void attn_mma(
    const __half* __restrict__ qkv1, __half* __restrict__ att1)
{
    extern __shared__ char sm[];
    const uint32_t sb = smem_u32(sm);
    const uint32_t Qs = sb, ST0 = sb + 16384;

    const int tid = threadIdx.x, lane = tid & 31, wid = tid >> 5;
    const int qb = blockIdx.x, h = blockIdx.y, b = blockIdx.z;
    const int lrow = lane & 15, lhalf = lane >> 4;
    const size_t rowbase = (size_t)b * SEQ;
    const __half* qg  = qkv1 + (rowbase + qb * 128) * 3072 + h * 64;
    const __half* kvg = qkv1 + rowbase * 3072 + h * 64;

    // Q tile load
#pragma unroll
    for (int i = 0; i < 4; i++) {
        int id = tid + 256 * i;            // 0..1023 -> 128 rows x 8 chunks
        int r = id >> 3, c = id & 7;
        uint32_t soff = r * 128 + ((c ^ (r & 7)) << 4);
        cpasync16(Qs + soff, qg + (size_t)r * 3072 + c * 8);
    }
    CP_COMMIT();
    attn_load_kv(ST0,         kvg,             tid); CP_COMMIT();
    attn_load_kv(ST0 + 16384, kvg + 64 * 3072, tid); CP_COMMIT();

    // Q fragments to registers
    asm volatile("cp.async.wait_group 2;" ::: "memory");
    __syncthreads();
    uint32_t qf[4][4];
    {
        int r = wid * 16 + lrow;
        uint32_t ro = (uint32_t)r * 128;
        int xv = r & 7;
#pragma unroll
        for (int ds = 0; ds < 4; ds++) {
            uint32_t co = (uint32_t)(((ds * 2 + lhalf) ^ xv) << 4);
            ldsm4(qf[ds], Qs + ro + co);
        }
    }

    float oacc[8][4];
#pragma unroll
    for (int t = 0; t < 8; t++)
#pragma unroll
        for (int q = 0; q < 4; q++) oacc[t][q] = 0.f;
    float m0 = -1e30f, m1 = -1e30f, l0 = 0.f, l1 = 0.f;

    const int kxv = lrow & 7;
    for (int kt = 0; kt < 32; kt++) {
        if (kt == 31) asm volatile("cp.async.wait_group 0;" ::: "memory");
        else          asm volatile("cp.async.wait_group 1;" ::: "memory");
        __syncthreads();
        const uint32_t st = ST0 + (uint32_t)(kt & 1) * 16384;

        // ---- S = Q K^T
        float sacc[8][4];
#pragma unroll
        for (int t = 0; t < 8; t++)
#pragma unroll
            for (int q = 0; q < 4; q++) sacc[t][q] = 0.f;

#pragma unroll
        for (int ds = 0; ds < 4; ds++) {
            uint32_t kh[4][4];
            const uint32_t co = (uint32_t)(((ds * 2 + lhalf) ^ kxv) << 4);
#pragma unroll
            for (int g = 0; g < 4; g++)
                ldsm4(kh[g], st + (uint32_t)(g * 16 + lrow) * 128 + co);
#pragma unroll
            for (int g = 0; g < 4; g++)
#pragma unroll
                for (int sel = 0; sel < 2; sel++)
                    mma16816(sacc[g * 2 + sel], qf[ds], kh[g][sel], kh[g][sel + 2]);
        }

        // ---- online softmax
        float mx0 = sacc[0][0], mx1 = sacc[0][2];
#pragma unroll
        for (int t = 0; t < 8; t++) {
            mx0 = fmaxf(mx0, fmaxf(sacc[t][0], sacc[t][1]));
            mx1 = fmaxf(mx1, fmaxf(sacc[t][2], sacc[t][3]));
        }
        mx0 = fmaxf(mx0, __shfl_xor_sync(0xffffffffu, mx0, 1));
        mx0 = fmaxf(mx0, __shfl_xor_sync(0xffffffffu, mx0, 2));
        mx1 = fmaxf(mx1, __shfl_xor_sync(0xffffffffu, mx1, 1));
        mx1 = fmaxf(mx1, __shfl_xor_sync(0xffffffffu, mx1, 2));
        const float mn0 = fmaxf(m0, mx0), mn1 = fmaxf(m1, mx1);
        const float a0 = ex2((m0 - mn0) * C1), a1 = ex2((m1 - mn1) * C1);
        const float mc0 = mn0 * C1, mc1 = mn1 * C1;
        float ls0 = 0.f, ls1 = 0.f;
#pragma unroll
        for (int t = 0; t < 8; t++) {
            sacc[t][0] = ex2(fmaf(sacc[t][0], C1, -mc0));
            sacc[t][1] = ex2(fmaf(sacc[t][1], C1, -mc0));
            sacc[t][2] = ex2(fmaf(sacc[t][2], C1, -mc1));
            sacc[t][3] = ex2(fmaf(sacc[t][3], C1, -mc1));
            ls0 += sacc[t][0] + sacc[t][1];
            ls1 += sacc[t][2] + sacc[t][3];
        }
        ls0 += __shfl_xor_sync(0xffffffffu, ls0, 1);
        ls0 += __shfl_xor_sync(0xffffffffu, ls0, 2);
        ls1 += __shfl_xor_sync(0xffffffffu, ls1, 1);
        ls1 += __shfl_xor_sync(0xffffffffu, ls1, 2);
        m0 = mn0; m1 = mn1;
        l0 = l0 * a0 + ls0; l1 = l1 * a1 + ls1;
#pragma unroll
        for (int t = 0; t < 8; t++) {
            oacc[t][0] *= a0; oacc[t][1] *= a0;
            oacc[t][2] *= a1; oacc[t][3] *= a1;
        }

        // ---- O += P V
#pragma unroll
        for (int kg = 0; kg < 4; kg++) {
            uint32_t aph[4];
            {
                const float* t0 = sacc[2 * kg];
                const float* t1 = sacc[2 * kg + 1];
                aph[0] = pack_h2(t0[0], t0[1]);
                aph[1] = pack_h2(t0[2], t0[3]);
                aph[2] = pack_h2(t1[0], t1[1]);
                aph[3] = pack_h2(t1[2], t1[3]);
            }
            const uint32_t vro = st + 8192 + (uint32_t)(kg * 16 + lrow) * 128;
#pragma unroll
            for (int dg = 0; dg < 4; dg++) {
                uint32_t vh[4];
                ldsm4t(vh, vro + (uint32_t)(((dg * 2 + lhalf) ^ kxv) << 4));
#pragma unroll
                for (int sel = 0; sel < 2; sel++)
                    mma16816(oacc[dg * 2 + sel], aph, vh[2 * sel], vh[2 * sel + 1]);
            }
        }
        __syncthreads();
        if (kt + 2 < 32) {
            attn_load_kv(ST0 + (uint32_t)(kt & 1) * 16384,
                         kvg + (size_t)(kt + 2) * 64 * 3072, tid);
            CP_COMMIT();
        }
    }

    // ---- epilogue
    const float inv0 = 1.0f / l0, inv1 = 1.0f / l1;
    const size_t grow = rowbase + (size_t)qb * 128 + wid * 16 + (lane >> 2);
#pragma unroll
    for (int t = 0; t < 8; t++) {
        const int col = h * 64 + t * 8 + (lane & 3) * 2;
        *(uint32_t*)(att1 + grow * 1024 + col) =
            pack_h2(oacc[t][0] * inv0, oacc[t][1] * inv0);
        *(uint32_t*)(att1 + (grow + 8) * 1024 + col) =
            pack_h2(oacc[t][2] * inv1, oacc[t][3] * inv1);
    }
}

// ---------------------------------------------------------------------------
// Host side
// ---------------------------------------------------------------------------
extern "C" void kernel_launch(void* const* d_in, const int* in_sizes, int n_in,
                              void* d_out, int out_size)
{
    (void)in_sizes; (void)n_in; (void)out_size;
    const float* x     = (const float*)d_in[0];
    const float* w_qkv = (const float*)d_in[1];
    const float* b_qkv = (const float*)d_in[2];
    const float* w_out = (const float*)d_in[3];
    const float* b_out = (const float*)d_in[4];
    float* out = (float*)d_out;

    __half *x1, *qkv1, *att1, *wq2, *wo2;
    cudaGetSymbolAddress((void**)&x1,   g_x1);
    cudaGetSymbolAddress((void**)&qkv1, g_qkv1);
    cudaGetSymbolAddress((void**)&att1, g_att1);
    cudaGetSymbolAddress((void**)&wq2,  g_wq2);
    cudaGetSymbolAddress((void**)&wo2,  g_wo2);

    cudaFuncSetAttribute(mma_gemm<true>,
                         cudaFuncAttributeMaxDynamicSharedMemorySize, GEMM_SMEM);
    cudaFuncSetAttribute(mma_gemm<false>,
                         cudaFuncAttributeMaxDynamicSharedMemorySize, GEMM_SMEM);
    cudaFuncSetAttribute(attn_mma, cudaFuncAttributeMaxDynamicSharedMemorySize, AT_SMEM);

    // 1) operand prep (single fused launch)
    prep_all<<<PREP_BLOCKS, 256>>>(x, x1, w_qkv, wq2, w_out, wo2);

    // 2) QKV projection -> fp16 qkv
    mma_gemm<true><<<dim3(QKVN / BN, MROWS / BM), 256, GEMM_SMEM>>>(
        x1, wq2, b_qkv, qkv1, QKVN);

    // 3) tensor-core flash attention -> fp16 att
    attn_mma<<<dim3(SEQ / 128, NHEAD, BATCH), 256, AT_SMEM>>>(qkv1, att1);

    // 4) output projection -> fp32 out
    mma_gemm<false><<<dim3(EMBED / BN, MROWS / BM), 256, GEMM_SMEM>>>(
        att1, wo2, b_out, out, EMBED);
}

// round 17
// speedup vs baseline: 1.1140x; 1.0014x over previous
#include <cuda_runtime.h>
#include <cuda_fp16.h>
#include <cstdint>

#define EMBED   1024
#define NHEAD   16
#define HD      64
#define SEQ     2048
#define BATCH   4
#define MROWS   (BATCH * SEQ)      /* 8192 */
#define QKVN    (3 * EMBED)        /* 3072 */
#define KDIM    1024

// ---------------------------------------------------------------------------
// Scratch (device globals -- runtime allocation is forbidden)
// ---------------------------------------------------------------------------
static __device__ __half g_x1  [(size_t)MROWS * KDIM];       // x fp16
static __device__ __half g_qkv1[(size_t)MROWS * QKVN];       // qkv fp16
static __device__ __half g_att1[(size_t)MROWS * KDIM];       // attn out fp16
static __device__ __half g_wq2 [(size_t)QKVN  * KDIM];       // w_qkv^T fp16
static __device__ __half g_wo2 [(size_t)EMBED * KDIM];       // w_out^T fp16

// ---------------------------------------------------------------------------
// PTX helpers (baseline ISA; griddepcontrol is sm_90 baseline, ok on sm_103)
// ---------------------------------------------------------------------------
__device__ __forceinline__ uint32_t smem_u32(const void* p) {
    uint32_t a;
    asm("{ .reg .u64 t; cvta.to.shared.u64 t, %1; cvt.u32.u64 %0, t; }"
        : "=r"(a) : "l"(p));
    return a;
}
__device__ __forceinline__ void cpasync16(uint32_t dst, const void* src) {
    asm volatile("cp.async.cg.shared.global [%0], [%1], 16;"
        :: "r"(dst), "l"(src) : "memory");
}
#define CP_COMMIT() asm volatile("cp.async.commit_group;" ::: "memory")

__device__ __forceinline__ void griddep_wait() {
    asm volatile("griddepcontrol.wait;" ::: "memory");
}
__device__ __forceinline__ void griddep_launch_dependents() {
    asm volatile("griddepcontrol.launch_dependents;");
}

__device__ __forceinline__ void ldsm4(uint32_t* r, uint32_t addr) {
    asm volatile("ldmatrix.sync.aligned.m8n8.x4.shared.b16 {%0,%1,%2,%3}, [%4];"
        : "=r"(r[0]), "=r"(r[1]), "=r"(r[2]), "=r"(r[3]) : "r"(addr));
}
__device__ __forceinline__ void ldsm4t(uint32_t* r, uint32_t addr) {
    asm volatile("ldmatrix.sync.aligned.m8n8.x4.trans.shared.b16 {%0,%1,%2,%3}, [%4];"
        : "=r"(r[0]), "=r"(r[1]), "=r"(r[2]), "=r"(r[3]) : "r"(addr));
}
// fp16 MMA, fp32 accumulate
__device__ __forceinline__ void mma16816(float* c, const uint32_t* a,
                                         uint32_t b0, uint32_t b1) {
    asm volatile(
        "mma.sync.aligned.m16n8k16.row.col.f32.f16.f16.f32 "
        "{%0,%1,%2,%3}, {%4,%5,%6,%7}, {%8,%9}, {%0,%1,%2,%3};"
        : "+f"(c[0]), "+f"(c[1]), "+f"(c[2]), "+f"(c[3])
        : "r"(a[0]), "r"(a[1]), "r"(a[2]), "r"(a[3]), "r"(b0), "r"(b1));
}
__device__ __forceinline__ float ex2(float x) {
    float y; asm("ex2.approx.f32 %0, %1;" : "=f"(y) : "f"(x)); return y;
}
__device__ __forceinline__ uint32_t pack_h2(float x, float y) {
    __half2 h = __floats2half2_rn(x, y);
    return *(uint32_t*)&h;
}

// ---------------------------------------------------------------------------
// operand prep: single fused kernel.
// blocks [0, 8192)      : x fp32 -> fp16 (rowwise cast)
// blocks [8192, 11264)  : w_qkv transpose+cast (96 x 32 tiles)
// blocks [11264, 12288) : w_out transpose+cast (32 x 32 tiles)
// ---------------------------------------------------------------------------
#define NB_CAST 8192
#define NB_WQ   3072
#define PREP_BLOCKS (NB_CAST + NB_WQ + 1024)

__device__ __forceinline__ void transpose_tile(
    const float* __restrict__ w, __half* __restrict__ out, int N,
    int n0, int k0, float (*t)[33], int tid)
{
    const int tx = tid & 31, ty = tid >> 5;
#pragma unroll
    for (int i = 0; i < 4; i++)
        t[ty + 8 * i][tx] = w[(size_t)(k0 + ty + 8 * i) * N + n0 + tx];
    __syncthreads();
#pragma unroll
    for (int i = 0; i < 4; i++) {
        int nl = ty + 8 * i;
        out[(size_t)(n0 + nl) * KDIM + k0 + tx] = __float2half_rn(t[tx][nl]);
    }
}

__global__ __launch_bounds__(256) void prep_all(
    const float* __restrict__ x,     __half* __restrict__ x1,
    const float* __restrict__ wq,    __half* __restrict__ wq2,
    const float* __restrict__ wo,    __half* __restrict__ wo2)
{
    __shared__ float t[32][33];
    const int b = blockIdx.x, tid = threadIdx.x;
    griddep_launch_dependents();
    if (b < NB_CAST) {
        size_t i4 = (size_t)b * 256 + tid;
        float4 v = *(const float4*)(x + i4 * 4);
        *(__half2*)(x1 + i4 * 4)     = __floats2half2_rn(v.x, v.y);
        *(__half2*)(x1 + i4 * 4 + 2) = __floats2half2_rn(v.z, v.w);
    } else if (b < NB_CAST + NB_WQ) {
        int bb = b - NB_CAST;
        transpose_tile(wq, wq2, QKVN, (bb % 96) * 32, (bb / 96) * 32, t, tid);
    } else {
        int bb = b - NB_CAST - NB_WQ;
        transpose_tile(wo, wo2, EMBED, (bb % 32) * 32, (bb / 32) * 32, t, tid);
    }
}

// ---------------------------------------------------------------------------
// mma.sync fp16 GEMM (2 CTAs/SM, plain fragment loads).
// CTA 128x128, warp tile 64x32 (2Mx4N), BK=64, 3-stage cp.async (32KB/stage).
// SPLIT=true : C fp16 [M,ldc] + bias.   SPLIT=false: C fp32 [M,ldc] + bias.
// Opens with griddepcontrol.wait (PDL dependent); signals dependents early.
// ---------------------------------------------------------------------------
#define BM 128
#define BN 128
#define BK 64
#define NK (KDIM / BK)            /* 16 */
#define NSTAGE 3
#define STG_BYTES 32768
#define GEMM_SMEM (NSTAGE * STG_BYTES)   /* 98304 */

__device__ __forceinline__ void gemm_load_stage(
    uint32_t sbase, const __half* __restrict__ A, const __half* __restrict__ B1,
    int m0, int n0, int kt, int tid)
{
    const int k0 = kt * BK;
#pragma unroll
    for (int i = 0; i < 4; i++) {
        int id = tid + 256 * i;            // 0..1023: 128 rows x 8 chunks
        int r = id >> 3;
        int c = id & 7;
        uint32_t soff = r * 128 + ((c ^ (r & 7)) << 4);
        cpasync16(sbase + soff,         A  + (size_t)(m0 + r) * KDIM + k0 + c * 8);
        cpasync16(sbase + 16384 + soff, B1 + (size_t)(n0 + r) * KDIM + k0 + c * 8);
    }
}

template<bool SPLIT>
__global__ __launch_bounds__(256, 2) void mma_gemm(
    const __half* __restrict__ A, const __half* __restrict__ B1,
    const float* __restrict__ bias, void* __restrict__ Cv, int ldc)
{
    extern __shared__ char sm[];
    const uint32_t sb = smem_u32(sm);
    const int tid  = threadIdx.x;
    const int lane = tid & 31;
    const int wid  = tid >> 5;
    const int wm   = wid & 1;
    const int wn   = wid >> 1;
    const int m0 = blockIdx.y * BM;
    const int n0 = blockIdx.x * BN;

    const int lrow  = lane & 15;
    const int lhalf = lane >> 4;
    const int xorv  = lrow & 7;

    uint32_t arow[4], brow[2];
#pragma unroll
    for (int mt = 0; mt < 4; mt++) arow[mt] = (wm * 64 + mt * 16 + lrow) * 128;
#pragma unroll
    for (int nt2 = 0; nt2 < 2; nt2++)
        brow[nt2] = 16384u + (wn * 32 + nt2 * 16 + lrow) * 128;

    float acc[4][4][4];
#pragma unroll
    for (int i = 0; i < 4; i++)
#pragma unroll
        for (int j = 0; j < 4; j++)
#pragma unroll
            for (int q = 0; q < 4; q++) acc[i][j][q] = 0.f;

    // PDL: let our dependents begin launching; wait for our producer's data.
    griddep_launch_dependents();
    griddep_wait();

    gemm_load_stage(sb,             A, B1, m0, n0, 0, tid); CP_COMMIT();
    gemm_load_stage(sb + STG_BYTES, A, B1, m0, n0, 1, tid); CP_COMMIT();

    for (int kt = 0; kt < NK; kt++) {
        if (kt < NK - 2) {
            gemm_load_stage(sb + ((kt + 2) % NSTAGE) * STG_BYTES, A, B1, m0, n0, kt + 2, tid);
            CP_COMMIT();
            asm volatile("cp.async.wait_group 2;" ::: "memory");
        } else if (kt == NK - 2) {
            asm volatile("cp.async.wait_group 1;" ::: "memory");
        } else {
            asm volatile("cp.async.wait_group 0;" ::: "memory");
        }
        __syncthreads();

        const uint32_t st = sb + (kt % NSTAGE) * STG_BYTES;
#pragma unroll
        for (int ks = 0; ks < 4; ks++) {
            const uint32_t coff = (uint32_t)(((ks * 2 + lhalf) ^ xorv) << 4);
            uint32_t ah[4][4], bh[2][4];
#pragma unroll
            for (int mt = 0; mt < 4; mt++) ldsm4(ah[mt], st + arow[mt] + coff);
#pragma unroll
            for (int nt2 = 0; nt2 < 2; nt2++) ldsm4(bh[nt2], st + brow[nt2] + coff);
#pragma unroll
            for (int mt = 0; mt < 4; mt++)
#pragma unroll
                for (int nt = 0; nt < 4; nt++) {
                    const int n2 = nt >> 1, sel = nt & 1;
                    mma16816(acc[mt][nt], ah[mt], bh[n2][sel], bh[n2][sel + 2]);
                }
        }
        __syncthreads();
    }

#pragma unroll
    for (int nt = 0; nt < 4; nt++) {
        const int col = n0 + wn * 32 + nt * 8 + (lane & 3) * 2;
        const float bx = __ldg(bias + col);
        const float by = __ldg(bias + col + 1);
#pragma unroll
        for (int mt = 0; mt < 4; mt++) {
            const int row = m0 + wm * 64 + mt * 16 + (lane >> 2);
            if (SPLIT) {
                __half* Cb = (__half*)Cv;
                *(uint32_t*)(Cb + (size_t)row * ldc + col) =
                    pack_h2(acc[mt][nt][0] + bx, acc[mt][nt][1] + by);
                *(uint32_t*)(Cb + (size_t)(row + 8) * ldc + col) =
                    pack_h2(acc[mt][nt][2] + bx, acc[mt][nt][3] + by);
            } else {
                float* C = (float*)Cv;
                float2 v0 = make_float2(acc[mt][nt][0] + bx, acc[mt][nt][1] + by);
                float2 v1 = make_float2(acc[mt][nt][2] + bx, acc[mt][nt][3] + by);
                *(float2*)(C + (size_t)row * ldc + col)       = v0;
                *(float2*)(C + (size_t)(row + 8) * ldc + col) = v1;
            }
        }
    }
}

// ---------------------------------------------------------------------------
// Tensor-core flash attention, all-fp16 operands (R13 form, depth-2 KV).
// Per CTA: 128 q-rows, one (b,h). 8 warps x 16 rows. Key tiles of 64.
// smem: Q 16K | 2 stages of {K 8K | V 8K} = 48KB -> 2 CTAs/SM.
// qkv1 row layout: [q(1024) k(1024) v(1024)], row stride 3072.
// ---------------------------------------------------------------------------
#define AT_SMEM (16384 + 2 * 16384)   /* 49152 */
#define C1 0.18033688f                /* 0.125 * log2(e) */

__device__ __forceinline__ void attn_load_kv(
    uint32_t stage, const __half* __restrict__ kvb, int tid)
{
#pragma unroll
    for (int i = 0; i < 2; i++) {
        int id = tid + 256 * i;            // 0..511 -> 64 rows x 8 chunks
        int r = id >> 3, c = id & 7;
        uint32_t soff = r * 128 + ((c ^ (r & 7)) << 4);
        const __half* g = kvb + (size_t)r * 3072 + c * 8;
        cpasync16(stage +        soff, g + 1024);   // K
        cpasync16(stage + 8192 + soff, g + 2048);   // V
    }
}

__global__ __launch_bounds__(256, 2) void attn_mma(
    const __half* __restrict__ qkv1, __half* __restrict__ att1)
{
    extern __shared__ char sm[];
    const uint32_t sb = smem_u32(sm);
    const uint32_t Qs = sb, ST0 = sb + 16384;

    const int tid = threadIdx.x, lane = tid & 31, wid = tid >> 5;
    const int qb = blockIdx.x, h = blockIdx.y, b = blockIdx.z;
    const int lrow = lane & 15, lhalf = lane >> 4;
    const size_t rowbase = (size_t)b * SEQ;
    const __half* qg  = qkv1 + (rowbase + qb * 128) * 3072 + h * 64;
    const __half* kvg = qkv1 + rowbase * 3072 + h * 64;

    // PDL: release dependents; wait for GEMM1's qkv to be visible.
    griddep_launch_dependents();
    griddep_wait();

    // Q tile load
#pragma unroll
    for (int i = 0; i < 4; i++) {
        int id = tid + 256 * i;            // 0..1023 -> 128 rows x 8 chunks
        int r = id >> 3, c = id & 7;
        uint32_t soff = r * 128 + ((c ^ (r & 7)) << 4);
        cpasync16(Qs + soff, qg + (size_t)r * 3072 + c * 8);
    }
    CP_COMMIT();
    attn_load_kv(ST0,         kvg,             tid); CP_COMMIT();
    attn_load_kv(ST0 + 16384, kvg + 64 * 3072, tid); CP_COMMIT();

    // Q fragments to registers
    asm volatile("cp.async.wait_group 2;" ::: "memory");
    __syncthreads();
    uint32_t qf[4][4];
    {
        int r = wid * 16 + lrow;
        uint32_t ro = (uint32_t)r * 128;
        int xv = r & 7;
#pragma unroll
        for (int ds = 0; ds < 4; ds++) {
            uint32_t co = (uint32_t)(((ds * 2 + lhalf) ^ xv) << 4);
            ldsm4(qf[ds], Qs + ro + co);
        }
    }

    float oacc[8][4];
#pragma unroll
    for (int t = 0; t < 8; t++)
#pragma unroll
        for (int q = 0; q < 4; q++) oacc[t][q] = 0.f;
    float m0 = -1e30f, m1 = -1e30f, l0 = 0.f, l1 = 0.f;

    const int kxv = lrow & 7;
    for (int kt = 0; kt < 32; kt++) {
        if (kt == 31) asm volatile("cp.async.wait_group 0;" ::: "memory");
        else          asm volatile("cp.async.wait_group 1;" ::: "memory");
        __syncthreads();
        const uint32_t st = ST0 + (uint32_t)(kt & 1) * 16384;

        // ---- S = Q K^T
        float sacc[8][4];
#pragma unroll
        for (int t = 0; t < 8; t++)
#pragma unroll
            for (int q = 0; q < 4; q++) sacc[t][q] = 0.f;

#pragma unroll
        for (int ds = 0; ds < 4; ds++) {
            uint32_t kh[4][4];
            const uint32_t co = (uint32_t)(((ds * 2 + lhalf) ^ kxv) << 4);
#pragma unroll
            for (int g = 0; g < 4; g++)
                ldsm4(kh[g], st + (uint32_t)(g * 16 + lrow) * 128 + co);
#pragma unroll
            for (int g = 0; g < 4; g++)
#pragma unroll
                for (int sel = 0; sel < 2; sel++)
                    mma16816(sacc[g * 2 + sel], qf[ds], kh[g][sel], kh[g][sel + 2]);
        }

        // ---- online softmax
        float mx0 = sacc[0][0], mx1 = sacc[0][2];
#pragma unroll
        for (int t = 0; t < 8; t++) {
            mx0 = fmaxf(mx0, fmaxf(sacc[t][0], sacc[t][1]));
            mx1 = fmaxf(mx1, fmaxf(sacc[t][2], sacc[t][3]));
        }
        mx0 = fmaxf(mx0, __shfl_xor_sync(0xffffffffu, mx0, 1));
        mx0 = fmaxf(mx0, __shfl_xor_sync(0xffffffffu, mx0, 2));
        mx1 = fmaxf(mx1, __shfl_xor_sync(0xffffffffu, mx1, 1));
        mx1 = fmaxf(mx1, __shfl_xor_sync(0xffffffffu, mx1, 2));
        const float mn0 = fmaxf(m0, mx0), mn1 = fmaxf(m1, mx1);
        const float a0 = ex2((m0 - mn0) * C1), a1 = ex2((m1 - mn1) * C1);
        const float mc0 = mn0 * C1, mc1 = mn1 * C1;
        float ls0 = 0.f, ls1 = 0.f;
#pragma unroll
        for (int t = 0; t < 8; t++) {
            sacc[t][0] = ex2(fmaf(sacc[t][0], C1, -mc0));
            sacc[t][1] = ex2(fmaf(sacc[t][1], C1, -mc0));
            sacc[t][2] = ex2(fmaf(sacc[t][2], C1, -mc1));
            sacc[t][3] = ex2(fmaf(sacc[t][3], C1, -mc1));
            ls0 += sacc[t][0] + sacc[t][1];
            ls1 += sacc[t][2] + sacc[t][3];
        }
        ls0 += __shfl_xor_sync(0xffffffffu, ls0, 1);
        ls0 += __shfl_xor_sync(0xffffffffu, ls0, 2);
        ls1 += __shfl_xor_sync(0xffffffffu, ls1, 1);
        ls1 += __shfl_xor_sync(0xffffffffu, ls1, 2);
        m0 = mn0; m1 = mn1;
        l0 = l0 * a0 + ls0; l1 = l1 * a1 + ls1;
#pragma unroll
        for (int t = 0; t < 8; t++) {
            oacc[t][0] *= a0; oacc[t][1] *= a0;
            oacc[t][2] *= a1; oacc[t][3] *= a1;
        }

        // ---- O += P V
#pragma unroll
        for (int kg = 0; kg < 4; kg++) {
            uint32_t aph[4];
            {
                const float* t0 = sacc[2 * kg];
                const float* t1 = sacc[2 * kg + 1];
                aph[0] = pack_h2(t0[0], t0[1]);
                aph[1] = pack_h2(t0[2], t0[3]);
                aph[2] = pack_h2(t1[0], t1[1]);
                aph[3] = pack_h2(t1[2], t1[3]);
            }
            const uint32_t vro = st + 8192 + (uint32_t)(kg * 16 + lrow) * 128;
#pragma unroll
            for (int dg = 0; dg < 4; dg++) {
                uint32_t vh[4];
                ldsm4t(vh, vro + (uint32_t)(((dg * 2 + lhalf) ^ kxv) << 4));
#pragma unroll
                for (int sel = 0; sel < 2; sel++)
                    mma16816(oacc[dg * 2 + sel], aph, vh[2 * sel], vh[2 * sel + 1]);
            }
        }
        __syncthreads();
        if (kt + 2 < 32) {
            attn_load_kv(ST0 + (uint32_t)(kt & 1) * 16384,
                         kvg + (size_t)(kt + 2) * 64 * 3072, tid);
            CP_COMMIT();
        }
    }

    // ---- epilogue
    const float inv0 = 1.0f / l0, inv1 = 1.0f / l1;
    const size_t grow = rowbase + (size_t)qb * 128 + wid * 16 + (lane >> 2);
#pragma unroll
    for (int t = 0; t < 8; t++) {
        const int col = h * 64 + t * 8 + (lane & 3) * 2;
        *(uint32_t*)(att1 + grow * 1024 + col) =
            pack_h2(oacc[t][0] * inv0, oacc[t][1] * inv0);
        *(uint32_t*)(att1 + (grow + 8) * 1024 + col) =
            pack_h2(oacc[t][2] * inv1, oacc[t][3] * inv1);
    }
}

// ---------------------------------------------------------------------------
// Host side: PDL-chained launches (programmatic stream serialization)
// ---------------------------------------------------------------------------
template<typename K, typename... Args>
static void launch_pdl(K kernel, dim3 grid, dim3 block, size_t smem,
                       bool pdl, Args... args)
{
    cudaLaunchConfig_t cfg = {};
    cfg.gridDim = grid;
    cfg.blockDim = block;
    cfg.dynamicSmemBytes = smem;
    cfg.stream = 0;
    cudaLaunchAttribute attr[1];
    if (pdl) {
        attr[0].id = cudaLaunchAttributeProgrammaticStreamSerialization;
        attr[0].val.programmaticStreamSerializationAllowed = 1;
        cfg.attrs = attr;
        cfg.numAttrs = 1;
    }
    cudaLaunchKernelEx(&cfg, kernel, args...);
}

extern "C" void kernel_launch(void* const* d_in, const int* in_sizes, int n_in,
                              void* d_out, int out_size)
{
    (void)in_sizes; (void)n_in; (void)out_size;
    const float* x     = (const float*)d_in[0];
    const float* w_qkv = (const float*)d_in[1];
    const float* b_qkv = (const float*)d_in[2];
    const float* w_out = (const float*)d_in[3];
    const float* b_out = (const float*)d_in[4];
    float* out = (float*)d_out;

    __half *x1, *qkv1, *att1, *wq2, *wo2;
    cudaGetSymbolAddress((void**)&x1,   g_x1);
    cudaGetSymbolAddress((void**)&qkv1, g_qkv1);
    cudaGetSymbolAddress((void**)&att1, g_att1);
    cudaGetSymbolAddress((void**)&wq2,  g_wq2);
    cudaGetSymbolAddress((void**)&wo2,  g_wo2);

    cudaFuncSetAttribute(mma_gemm<true>,
                         cudaFuncAttributeMaxDynamicSharedMemorySize, GEMM_SMEM);
    cudaFuncSetAttribute(mma_gemm<false>,
                         cudaFuncAttributeMaxDynamicSharedMemorySize, GEMM_SMEM);
    cudaFuncSetAttribute(attn_mma, cudaFuncAttributeMaxDynamicSharedMemorySize, AT_SMEM);

    // 1) operand prep (single fused launch; head of the PDL chain)
    launch_pdl(prep_all, dim3(PREP_BLOCKS), dim3(256), 0, false,
               x, x1, w_qkv, wq2, w_out, wo2);

    // 2) QKV projection -> fp16 qkv   (PDL dependent of prep)
    launch_pdl(mma_gemm<true>, dim3(QKVN / BN, MROWS / BM), dim3(256),
               (size_t)GEMM_SMEM, true,
               (const __half*)x1, (const __half*)wq2, b_qkv, (void*)qkv1, (int)QKVN);

    // 3) flash attention -> fp16 att  (PDL dependent of GEMM1)
    launch_pdl(attn_mma, dim3(SEQ / 128, NHEAD, BATCH), dim3(256),
               (size_t)AT_SMEM, true,
               (const __half*)qkv1, att1);

    // 4) output projection -> fp32 out (PDL dependent of attention)
    launch_pdl(mma_gemm<false>, dim3(EMBED / BN, MROWS / BM), dim3(256),
               (size_t)GEMM_SMEM, true,
               (const __half*)att1, (const __half*)wo2, b_out, (void*)out, (int)EMBED);
}